// round 3
// baseline (speedup 1.0000x reference)
#include <cuda_runtime.h>
#include <math.h>

#define T_STEPS 4096
#define BATCH   32
#define DIN     256
#define HID     256
#define GATES   1024            // 4*HID
#define OUTD    512
#define NBLK    128

// ---------------- scratch (static device allocations are allowed) ----------
__device__ float g_xz_f[(size_t)T_STEPS * BATCH * GATES];   // 512 MiB
__device__ float g_xz_b[(size_t)T_STEPS * BATCH * GATES];   // 512 MiB
__device__ float g_houts[(size_t)T_STEPS * BATCH * 2 * HID];// 256 MiB, [t][b][f|b]
__device__ float g_hbuf[2][BATCH * HID];                    // ping-pong h
__device__ unsigned g_bar_count;
__device__ unsigned g_bar_gen;

__global__ void k_init() { g_bar_count = 0u; g_bar_gen = 0u; }

// ---------------- grid-wide barrier (generation counter) -------------------
__device__ __forceinline__ void grid_sync(unsigned gen) {
    __syncthreads();
    if (threadIdx.x == 0) {
        __threadfence();
        unsigned prev = atomicAdd(&g_bar_count, 1u);
        if (prev == NBLK - 1) {
            g_bar_count = 0u;
            __threadfence();
            atomicExch(&g_bar_gen, gen);
        } else {
            volatile unsigned* vg = &g_bar_gen;
            while (*vg < gen) { }
        }
    }
    __syncthreads();
}

__device__ __forceinline__ float sigf(float x)  { return 1.0f / (1.0f + __expf(-x)); }
__device__ __forceinline__ float tanhf_(float x){ return 1.0f - 2.0f / (__expf(2.0f * x) + 1.0f); }

// ---------------- GEMM 1: xz = x @ Wx + bias  (M=131072, N=1024, K=256) ----
// A row m = b*4096+t (natural x order); C row = t*32+b (recurrence order).
__global__ void __launch_bounds__(256) k_gemm_xz(
    const float* __restrict__ A, const float* __restrict__ W,
    const float* __restrict__ bias, int sel)
{
    float* __restrict__ C = sel ? g_xz_b : g_xz_f;
    __shared__ float As[16][64];
    __shared__ float Bs[16][64];
    const int tid = threadIdx.x;
    const int n0 = blockIdx.x << 6;
    const int m0 = blockIdx.y << 6;
    const int tx = tid & 15, ty = tid >> 4;
    const int ia = tid >> 2, kka = (tid & 3) << 2;     // A loader
    const int kkb = tid >> 4, jb = (tid & 15) << 2;    // B loader
    float acc[4][4] = {};

    for (int k0 = 0; k0 < DIN; k0 += 16) {
        float4 av = *(const float4*)(A + (size_t)(m0 + ia) * DIN + k0 + kka);
        float4 bv = *(const float4*)(W + (size_t)(k0 + kkb) * GATES + n0 + jb);
        __syncthreads();
        As[kka + 0][ia] = av.x; As[kka + 1][ia] = av.y;
        As[kka + 2][ia] = av.z; As[kka + 3][ia] = av.w;
        *(float4*)&Bs[kkb][jb] = bv;
        __syncthreads();
#pragma unroll
        for (int kk = 0; kk < 16; kk++) {
            float4 a = *(const float4*)&As[kk][ty << 2];
            float4 b = *(const float4*)&Bs[kk][tx << 2];
            float ar[4] = {a.x, a.y, a.z, a.w};
            float br[4] = {b.x, b.y, b.z, b.w};
#pragma unroll
            for (int r = 0; r < 4; r++)
#pragma unroll
                for (int c = 0; c < 4; c++) acc[r][c] = fmaf(ar[r], br[c], acc[r][c]);
        }
    }
    float4 bi = *(const float4*)(bias + n0 + (tx << 2));
#pragma unroll
    for (int r = 0; r < 4; r++) {
        int m = m0 + (ty << 2) + r;
        int t = m & 4095, b = m >> 12;
        float4 o;
        o.x = acc[r][0] + bi.x; o.y = acc[r][1] + bi.y;
        o.z = acc[r][2] + bi.z; o.w = acc[r][3] + bi.w;
        *(float4*)(C + (size_t)(t * BATCH + b) * GATES + n0 + (tx << 2)) = o;
    }
}

// ---------------- GEMM 2: out = relu(h_cat) @ W_dense + b  (K=512, N=512) --
// A row m = t*32+b (g_houts order); C row -> out[b][t][:].
__global__ void __launch_bounds__(256) k_gemm_dense(
    const float* __restrict__ W, const float* __restrict__ bias,
    float* __restrict__ out)
{
    __shared__ float As[16][64];
    __shared__ float Bs[16][64];
    const int tid = threadIdx.x;
    const int n0 = blockIdx.x << 6;
    const int m0 = blockIdx.y << 6;
    const int tx = tid & 15, ty = tid >> 4;
    const int ia = tid >> 2, kka = (tid & 3) << 2;
    const int kkb = tid >> 4, jb = (tid & 15) << 2;
    float acc[4][4] = {};

    for (int k0 = 0; k0 < 2 * HID; k0 += 16) {
        float4 av = *(const float4*)(g_houts + (size_t)(m0 + ia) * (2 * HID) + k0 + kka);
        av.x = fmaxf(av.x, 0.f); av.y = fmaxf(av.y, 0.f);
        av.z = fmaxf(av.z, 0.f); av.w = fmaxf(av.w, 0.f);
        float4 bv = *(const float4*)(W + (size_t)(k0 + kkb) * OUTD + n0 + jb);
        __syncthreads();
        As[kka + 0][ia] = av.x; As[kka + 1][ia] = av.y;
        As[kka + 2][ia] = av.z; As[kka + 3][ia] = av.w;
        *(float4*)&Bs[kkb][jb] = bv;
        __syncthreads();
#pragma unroll
        for (int kk = 0; kk < 16; kk++) {
            float4 a = *(const float4*)&As[kk][ty << 2];
            float4 b = *(const float4*)&Bs[kk][tx << 2];
            float ar[4] = {a.x, a.y, a.z, a.w};
            float br[4] = {b.x, b.y, b.z, b.w};
#pragma unroll
            for (int r = 0; r < 4; r++)
#pragma unroll
                for (int c = 0; c < 4; c++) acc[r][c] = fmaf(ar[r], br[c], acc[r][c]);
        }
    }
    float4 bi = *(const float4*)(bias + n0 + (tx << 2));
#pragma unroll
    for (int r = 0; r < 4; r++) {
        int m = m0 + (ty << 2) + r;
        int b = m & 31, t = m >> 5;
        float4 o;
        o.x = acc[r][0] + bi.x; o.y = acc[r][1] + bi.y;
        o.z = acc[r][2] + bi.z; o.w = acc[r][3] + bi.w;
        *(float4*)(out + ((size_t)b * T_STEPS + t) * OUTD + n0 + (tx << 2)) = o;
    }
}

// ---------------- persistent recurrence kernel -----------------------------
// 128 blocks = 4 batch-groups (8 batches) x 32 col-groups (8 h-cols).
// Thread tid: seg = tid>>5 (k-segment of 32), oc = tid&31 = gate*8 + jl.
__global__ void __launch_bounds__(256, 1) k_recur(
    const float* __restrict__ carry_c, const float* __restrict__ carry_h,
    const float* __restrict__ Wh_f, const float* __restrict__ Wh_b)
{
    __shared__ float h_s[8 * 256];   // h for this block's 8 batches
    __shared__ float p_s[8 * 256];   // partials [seg][b][oc]
    __shared__ float z_s[256];       // z [b][oc]
    __shared__ float c_s[64];        // cell state [b][j]

    const int tid = threadIdx.x;
    const int bg = blockIdx.x >> 5;           // 0..3
    const int cg = blockIdx.x & 31;           // 0..31
    const int b0 = bg << 3;                   // first batch
    const int j0 = cg << 3;                   // first h-col
    const int seg = tid >> 5;
    const int oc = tid & 31;
    const int gate = oc >> 3, jl = oc & 7;
    const int bl6 = tid >> 5, oc6 = tid & 31; // stage-6 cell mapping
    const int g6 = oc6 >> 3, j6 = oc6 & 7;
    const int bl7 = tid >> 3, jl7 = tid & 7;  // stage-7 mapping (tid<64)

    if (tid < 64) c_s[tid] = carry_c[(size_t)(b0 + bl7) * HID + j0 + jl7];

    unsigned gen = 0;
    int gs = 0;   // global step 0..8191

    for (int dir = 0; dir < 2; dir++) {
        const float* __restrict__ Wh = dir ? Wh_b : Wh_f;
        const float* __restrict__ xz = dir ? g_xz_b : g_xz_f;
        const int half = dir ? HID : 0;

        // this thread's weight slice, register-resident for the whole scan
        float w[32];
#pragma unroll
        for (int kk = 0; kk < 32; kk++)
            w[kk] = Wh[(size_t)((seg << 5) + kk) * GATES + (gate << 8) + j0 + jl];

        for (int s = 0; s < T_STEPS; s++, gs++) {
            const int t = dir ? (T_STEPS - 1 - s) : s;
            if (gs) { gen++; grid_sync(gen); }

            // load h (8 batches x 256) from ping-pong buffer (L2, bypass L1)
            const float* hp = gs ? &g_hbuf[gs & 1][0] : carry_h;
            const float4* src = (const float4*)(hp + (b0 << 8));
            float4 v0 = __ldcg(src + tid);
            float4 v1 = __ldcg(src + tid + 256);
            // prefetch xz early (independent of h)
            float xzv = xz[((size_t)t * BATCH + b0 + bl6) * GATES + (g6 << 8) + j0 + j6];
            ((float4*)h_s)[tid] = v0;
            ((float4*)h_s)[tid + 256] = v1;
            __syncthreads();

            // partial dot products: 8 batches x 32 k against register weights
#pragma unroll
            for (int b = 0; b < 8; b++) {
                const float4* hh = (const float4*)&h_s[(b << 8) + (seg << 5)];
                float acc = 0.f;
#pragma unroll
                for (int q = 0; q < 8; q++) {
                    float4 hv = hh[q];
                    acc = fmaf(hv.x, w[4 * q + 0], acc);
                    acc = fmaf(hv.y, w[4 * q + 1], acc);
                    acc = fmaf(hv.z, w[4 * q + 2], acc);
                    acc = fmaf(hv.w, w[4 * q + 3], acc);
                }
                p_s[(seg << 8) + (b << 5) + oc] = acc;
            }
            __syncthreads();

            // reduce 8 segments + xz
            {
                float z = xzv;
#pragma unroll
                for (int sg2 = 0; sg2 < 8; sg2++) z += p_s[(sg2 << 8) + tid];
                z_s[tid] = z;
            }
            __syncthreads();

            // gates + state update + h publish
            if (tid < 64) {
                float zi = z_s[(bl7 << 5) + jl7];
                float zf = z_s[(bl7 << 5) + 8 + jl7];
                float zg = z_s[(bl7 << 5) + 16 + jl7];
                float zo = z_s[(bl7 << 5) + 24 + jl7];
                float c = fmaf(sigf(zf), c_s[tid], sigf(zi) * tanhf_(zg));
                float h = sigf(zo) * tanhf_(c);
                c_s[tid] = c;
                g_hbuf[(gs + 1) & 1][((b0 + bl7) << 8) + j0 + jl7] = h;
                g_houts[((size_t)t * BATCH + b0 + bl7) * (2 * HID) + half + j0 + jl7] = h;
            }
            // next-iter h_s overwrite is guarded by grid_sync's __syncthreads
        }
    }
}

// ---------------- launch ----------------------------------------------------
extern "C" void kernel_launch(void* const* d_in, const int* in_sizes, int n_in,
                              void* d_out, int out_size) {
    const float* carry_c = (const float*)d_in[0];
    const float* carry_h = (const float*)d_in[1];
    const float* x       = (const float*)d_in[2];
    const float* Wx_f    = (const float*)d_in[3];
    const float* Wh_f    = (const float*)d_in[4];
    const float* b_f     = (const float*)d_in[5];
    const float* Wx_b    = (const float*)d_in[6];
    const float* Wh_b    = (const float*)d_in[7];
    const float* b_b     = (const float*)d_in[8];
    const float* W_dense = (const float*)d_in[9];
    const float* b_dense = (const float*)d_in[10];
    float* out = (float*)d_out;

    k_init<<<1, 1>>>();

    dim3 g1(GATES / 64, (BATCH * T_STEPS) / 64);   // (16, 2048)
    k_gemm_xz<<<g1, 256>>>(x, Wx_f, b_f, 0);
    k_gemm_xz<<<g1, 256>>>(x, Wx_b, b_b, 1);

    k_recur<<<NBLK, 256>>>(carry_c, carry_h, Wh_f, Wh_b);

    dim3 g2(OUTD / 64, (BATCH * T_STEPS) / 64);    // (8, 2048)
    k_gemm_dense<<<g2, 256>>>(W_dense, b_dense, out);
}